// round 4
// baseline (speedup 1.0000x reference)
#include <cuda_runtime.h>
#include <math.h>

#define EPS 1e-8f

// Scratch (device globals: no allocation allowed)
__device__ float g_att[2][16][128][128];       // attention matrices (fw/bw)
__device__ float g_rowsum_fw[16][128];         // sum_j att_fw[b,i,j]
__device__ float g_meanS[2][16][128][256];     // att @ q2 (unnormalized mean)
__device__ float g_maxat[2][16][128][256];     // max_j att[i,j]*q2[j,h]

// ---------------------------------------------------------------------------
// Kernel 1: attention matrices  att[b,i,j] = <q1_i, q2_j> / clamp(|q1_i||q2_j|)
// grid (16 b, 2 dir, 4 = it*2+jt), 256 threads, 64x64 tile, 4x4 micro
// ---------------------------------------------------------------------------
__global__ void k_attention(const float* __restrict__ q1, const float* __restrict__ q2) {
    int b = blockIdx.x, dir = blockIdx.y;
    int it = blockIdx.z >> 1, jt = blockIdx.z & 1;
    const float* A = q1 + ((size_t)b * 128 + it * 64) * 512 + dir * 256;
    const float* B = q2 + ((size_t)b * 128 + jt * 64) * 512 + dir * 256;

    __shared__ float n1s[64], n2s[64];
    __shared__ float As[16][64], Bs[16][64];

    int t = threadIdx.x;
    if (t < 128) {
        int r = t & 63;
        const float* src = (t < 64) ? A : B;
        float s = 0.f;
        for (int h = 0; h < 256; h += 4) {
            float4 v = *(const float4*)(src + (size_t)r * 512 + h);
            s += v.x * v.x + v.y * v.y + v.z * v.z + v.w * v.w;
        }
        if (t < 64) n1s[r] = sqrtf(s); else n2s[r] = sqrtf(s);
    }

    int tx = t & 15, ty = t >> 4;
    float acc[4][4] = {};
    int iL = t >> 2, c4 = (t & 3) * 4;

    for (int k0 = 0; k0 < 256; k0 += 16) {
        float4 a  = *(const float4*)(A + (size_t)iL * 512 + k0 + c4);
        float4 bb = *(const float4*)(B + (size_t)iL * 512 + k0 + c4);
        As[c4 + 0][iL] = a.x;  As[c4 + 1][iL] = a.y;
        As[c4 + 2][iL] = a.z;  As[c4 + 3][iL] = a.w;
        Bs[c4 + 0][iL] = bb.x; Bs[c4 + 1][iL] = bb.y;
        Bs[c4 + 2][iL] = bb.z; Bs[c4 + 3][iL] = bb.w;
        __syncthreads();
#pragma unroll
        for (int kk = 0; kk < 16; kk++) {
            float4 ar = *(const float4*)&As[kk][ty * 4];
            float4 br = *(const float4*)&Bs[kk][tx * 4];
            float arr[4] = {ar.x, ar.y, ar.z, ar.w};
            float brr[4] = {br.x, br.y, br.z, br.w};
#pragma unroll
            for (int ii = 0; ii < 4; ii++)
#pragma unroll
                for (int jj = 0; jj < 4; jj++)
                    acc[ii][jj] += arr[ii] * brr[jj];
        }
        __syncthreads();
    }

#pragma unroll
    for (int ii = 0; ii < 4; ii++)
#pragma unroll
        for (int jj = 0; jj < 4; jj++) {
            int i = ty * 4 + ii, j = tx * 4 + jj;
            float den = n1s[i] * n2s[j];
            den = (den > EPS) ? den : EPS;      // div_small
            g_att[dir][b][it * 64 + i][jt * 64 + j] = acc[ii][jj] / den;
        }
}

// ---------------------------------------------------------------------------
// Kernel 1.5: rowsums of att_fw (used by BOTH mean_fw and mean_bw per ref)
// ---------------------------------------------------------------------------
__global__ void k_rowsum() {
    int b = blockIdx.x, i = threadIdx.x;   // 16 blocks x 128 threads
    float s = 0.f;
    const float* row = &g_att[0][b][i][0];
    for (int j = 0; j < 128; j++) s += row[j];
    g_rowsum_fw[b][i] = s;
}

// ---------------------------------------------------------------------------
// Kernel 2: meanS[i,h] = sum_j att[i,j]*q2[j,h];  maxat[i,h] = max_j ...
// grid (16 b, 2 dir, 4 i-quarters), 256 threads (one per h)
// ---------------------------------------------------------------------------
__global__ void k_meanmax(const float* __restrict__ q2) {
    int b = blockIdx.x, dir = blockIdx.y, iq = blockIdx.z;
    int i0 = iq * 32;
    __shared__ float att_s[32][128];   // 16 KB

    const float* src = &g_att[dir][b][i0][0];
    for (int c = threadIdx.x; c < 32 * 128; c += 256)
        ((float*)att_s)[c] = src[c];
    __syncthreads();

    int h = threadIdx.x;
    const float* B = q2 + (size_t)b * 65536 + dir * 256 + h;

    for (int il = 0; il < 32; il += 4) {
        float acc0 = 0.f, acc1 = 0.f, acc2 = 0.f, acc3 = 0.f;
        float mx0 = -INFINITY, mx1 = -INFINITY, mx2 = -INFINITY, mx3 = -INFINITY;
#pragma unroll 4
        for (int j = 0; j < 128; j++) {
            float q = __ldg(B + (size_t)j * 512);
            float v0 = att_s[il + 0][j] * q; acc0 += v0; mx0 = fmaxf(mx0, v0);
            float v1 = att_s[il + 1][j] * q; acc1 += v1; mx1 = fmaxf(mx1, v1);
            float v2 = att_s[il + 2][j] * q; acc2 += v2; mx2 = fmaxf(mx2, v2);
            float v3 = att_s[il + 3][j] * q; acc3 += v3; mx3 = fmaxf(mx3, v3);
        }
        g_meanS[dir][b][i0 + il + 0][h] = acc0;  g_maxat[dir][b][i0 + il + 0][h] = mx0;
        g_meanS[dir][b][i0 + il + 1][h] = acc1;  g_maxat[dir][b][i0 + il + 1][h] = mx1;
        g_meanS[dir][b][i0 + il + 2][h] = acc2;  g_maxat[dir][b][i0 + il + 2][h] = mx2;
        g_meanS[dir][b][i0 + il + 3][h] = acc3;  g_maxat[dir][b][i0 + il + 3][h] = mx3;
    }
}

// ---------------------------------------------------------------------------
// Kernel 3: cos_maxpool.  Per (b,p,dir): S = (q1 .* w2_p) q2^T (128x128x256),
// cos = S / clamp(na_i * nc_j), out = max_j cos.  Writes out cols 32..63.
// grid (16 b, 16 p, 2 dir), 256 threads, 8x8 micro-tile
// ---------------------------------------------------------------------------
__global__ void k_maxpool(const float* __restrict__ q1, const float* __restrict__ q2,
                          const float* __restrict__ W, float* __restrict__ out) {
    int b = blockIdx.x, p = blockIdx.y, dir = blockIdx.z;
    const float* A  = q1 + (size_t)b * 65536 + dir * 256;
    const float* B  = q2 + (size_t)b * 65536 + dir * 256;
    const float* Wp = W + (size_t)((2 + dir) * 16 + p) * 256;

    __shared__ float w2[256];
    __shared__ float na[128], nc[128];
    __shared__ float As[16][128], Bs[16][128];
    __shared__ float red[128][16];

    int t = threadIdx.x;
    { float w = Wp[t]; w2[t] = w * w; }
    __syncthreads();

    // weighted norms
    {
        int r = t & 127;
        const float* src = (t < 128) ? A : B;
        float s = 0.f;
        for (int h = 0; h < 256; h += 4) {
            float4 v = *(const float4*)(src + (size_t)r * 512 + h);
            s += v.x * v.x * w2[h] + v.y * v.y * w2[h + 1]
               + v.z * v.z * w2[h + 2] + v.w * v.w * w2[h + 3];
        }
        if (t < 128) na[r] = sqrtf(s); else nc[r] = sqrtf(s);
    }

    int tx = t & 15, ty = t >> 4;
    float acc[8][8] = {};

    for (int k0 = 0; k0 < 256; k0 += 16) {
#pragma unroll
        for (int r = 0; r < 2; r++) {
            int v = t * 2 + r;               // 0..511
            int iL = v >> 2, c4 = (v & 3) * 4;
            float4 a  = *(const float4*)(A + (size_t)iL * 512 + k0 + c4);
            float4 bb = *(const float4*)(B + (size_t)iL * 512 + k0 + c4);
            As[c4 + 0][iL] = a.x * w2[k0 + c4 + 0];
            As[c4 + 1][iL] = a.y * w2[k0 + c4 + 1];
            As[c4 + 2][iL] = a.z * w2[k0 + c4 + 2];
            As[c4 + 3][iL] = a.w * w2[k0 + c4 + 3];
            Bs[c4 + 0][iL] = bb.x; Bs[c4 + 1][iL] = bb.y;
            Bs[c4 + 2][iL] = bb.z; Bs[c4 + 3][iL] = bb.w;
        }
        __syncthreads();
#pragma unroll
        for (int kk = 0; kk < 16; kk++) {
            float ar[8], br[8];
            *(float4*)&ar[0] = *(const float4*)&As[kk][ty * 8];
            *(float4*)&ar[4] = *(const float4*)&As[kk][ty * 8 + 4];
            *(float4*)&br[0] = *(const float4*)&Bs[kk][tx * 8];
            *(float4*)&br[4] = *(const float4*)&Bs[kk][tx * 8 + 4];
#pragma unroll
            for (int ii = 0; ii < 8; ii++)
#pragma unroll
                for (int jj = 0; jj < 8; jj++)
                    acc[ii][jj] += ar[ii] * br[jj];
        }
        __syncthreads();
    }

#pragma unroll
    for (int ii = 0; ii < 8; ii++) {
        int i = ty * 8 + ii;
        float m = -INFINITY;
#pragma unroll
        for (int jj = 0; jj < 8; jj++) {
            int j = tx * 8 + jj;
            float den = fmaxf(na[i] * nc[j], EPS);
            m = fmaxf(m, __fdividef(acc[ii][jj], den));
        }
        red[i][tx] = m;
    }
    __syncthreads();
    if (t < 128) {
        float m = red[t][0];
#pragma unroll
        for (int x = 1; x < 16; x++) m = fmaxf(m, red[t][x]);
        out[((size_t)b * 128 + t) * 128 + 32 + dir * 16 + p] = m;
    }
}

// ---------------------------------------------------------------------------
// Kernel 4: the six cos_full outputs (full, attn, maxattn) x (fw, bw).
// grid (128 i, 16 b), 256 threads (8 warps). 96 (which,dir,p) tasks per CTA.
// Writes out cols 0..31, 64..95, 96..127.
// ---------------------------------------------------------------------------
__global__ void k_cosfull(const float* __restrict__ q1, const float* __restrict__ q2,
                          const float* __restrict__ W, float* __restrict__ out) {
    int i = blockIdx.x, b = blockIdx.y;
    int lane = threadIdx.x & 31, warp = threadIdx.x >> 5;

    for (int s = 0; s < 12; s++) {
        int tk = warp + 8 * s;            // 0..95
        int p = tk & 15;
        int rest = tk >> 4;               // 0..5
        int dir = rest & 1, which = rest >> 1;
        int widx = (which == 0) ? dir : ((which == 1) ? 4 + dir : 6 + dir);
        const float* wv = W + (size_t)(widx * 16 + p) * 256;
        const float* x  = q1 + (size_t)b * 65536 + (size_t)i * 512 + dir * 256;
        const float* y;
        float sy = 1.f;
        if (which == 0) {
            int j = (dir == 0) ? 127 : 0;  // fw: last q2 row, bw: first
            y = q2 + (size_t)b * 65536 + (size_t)j * 512 + dir * 256;
        } else if (which == 1) {
            y = &g_meanS[dir][b][i][0];
            float rs = g_rowsum_fw[b][i];              // ref uses att_fw sums for BOTH dirs
            float bsafe = (rs > EPS) ? rs : EPS;
            sy = 1.f / bsafe;
        } else {
            y = &g_maxat[dir][b][i][0];
        }

        float sxy = 0.f, sxx = 0.f, syy = 0.f;
        for (int h = lane; h < 256; h += 32) {
            float w = wv[h]; float ww = w * w;
            float xv = x[h];
            float yv = y[h] * sy;
            sxy += xv * yv * ww;
            sxx += xv * xv * ww;
            syy += yv * yv * ww;
        }
#pragma unroll
        for (int off = 16; off > 0; off >>= 1) {
            sxy += __shfl_xor_sync(0xffffffffu, sxy, off);
            sxx += __shfl_xor_sync(0xffffffffu, sxx, off);
            syy += __shfl_xor_sync(0xffffffffu, syy, off);
        }
        if (lane == 0) {
            float den = fmaxf(sqrtf(sxx) * sqrtf(syy), EPS);
            int col = ((which == 0) ? 0 : (which == 1) ? 64 : 96) + dir * 16 + p;
            out[((size_t)b * 128 + i) * 128 + col] = sxy / den;
        }
    }
}

// ---------------------------------------------------------------------------
extern "C" void kernel_launch(void* const* d_in, const int* in_sizes, int n_in,
                              void* d_out, int out_size) {
    const float* q1 = (const float*)d_in[0];
    const float* q2 = (const float*)d_in[1];
    const float* W  = (const float*)d_in[2];
    float* out = (float*)d_out;

    k_attention<<<dim3(16, 2, 4), 256>>>(q1, q2);
    k_rowsum<<<16, 128>>>();
    k_meanmax<<<dim3(16, 2, 4), 256>>>(q2);
    k_maxpool<<<dim3(16, 16, 2), 256>>>(q1, q2, W, out);
    k_cosfull<<<dim3(128, 16), 256>>>(q1, q2, W, out);
}

// round 8
// speedup vs baseline: 1.2156x; 1.2156x over previous
#include <cuda_runtime.h>
#include <cuda_bf16.h>
#include <cstdint>
#include <math.h>

#define EPS 1e-8f

// Scratch (device globals: no allocation allowed)
__device__ float g_att[2][16][128][128];       // attention matrices (fw/bw)
__device__ float g_rowsum_fw[16][128];         // sum_j att_fw[b,i,j]
__device__ float g_meanS[2][16][128][256];     // att @ q2 (unnormalized mean)
__device__ float g_maxat[2][16][128][256];     // max_j att[i,j]*q2[j,h]
__device__ __nv_bfloat16 g_q2h[16 * 128 * 512];  // q2 hi bf16
__device__ __nv_bfloat16 g_q2l[16 * 128 * 512];  // q2 lo bf16 (residual)

// ---------------------------------------------------------------------------
// mma.sync m16n8k16 bf16 (HMMA path — legal on plain sm_103 PTX target)
// ---------------------------------------------------------------------------
__device__ __forceinline__ void mma16816(float* d, const uint32_t* a, const uint32_t* b) {
    asm volatile(
        "mma.sync.aligned.m16n8k16.row.col.f32.bf16.bf16.f32 "
        "{%0,%1,%2,%3}, {%4,%5,%6,%7}, {%8,%9}, {%0,%1,%2,%3};"
        : "+f"(d[0]), "+f"(d[1]), "+f"(d[2]), "+f"(d[3])
        : "r"(a[0]), "r"(a[1]), "r"(a[2]), "r"(a[3]), "r"(b[0]), "r"(b[1]));
}

// ---------------------------------------------------------------------------
// Kernel 0: split q2 into hi/lo bf16 (p-independent, done once)
// ---------------------------------------------------------------------------
__global__ void k_split_q2(const float* __restrict__ q2) {
    int idx = blockIdx.x * 256 + threadIdx.x;    // 262144 float4 groups
    float4 v = *(const float4*)(q2 + (size_t)idx * 4);
    __nv_bfloat16 h0 = __float2bfloat16(v.x), h1 = __float2bfloat16(v.y);
    __nv_bfloat16 h2 = __float2bfloat16(v.z), h3 = __float2bfloat16(v.w);
    __nv_bfloat16 l0 = __float2bfloat16(v.x - __bfloat162float(h0));
    __nv_bfloat16 l1 = __float2bfloat16(v.y - __bfloat162float(h1));
    __nv_bfloat16 l2 = __float2bfloat16(v.z - __bfloat162float(h2));
    __nv_bfloat16 l3 = __float2bfloat16(v.w - __bfloat162float(h3));
    uint2 pk;
    pk.x = ((uint32_t)__bfloat16_as_ushort(h1) << 16) | __bfloat16_as_ushort(h0);
    pk.y = ((uint32_t)__bfloat16_as_ushort(h3) << 16) | __bfloat16_as_ushort(h2);
    ((uint2*)g_q2h)[idx] = pk;
    pk.x = ((uint32_t)__bfloat16_as_ushort(l1) << 16) | __bfloat16_as_ushort(l0);
    pk.y = ((uint32_t)__bfloat16_as_ushort(l3) << 16) | __bfloat16_as_ushort(l2);
    ((uint2*)g_q2l)[idx] = pk;
}

// ---------------------------------------------------------------------------
// Kernel 1: attention matrices
// ---------------------------------------------------------------------------
__global__ void k_attention(const float* __restrict__ q1, const float* __restrict__ q2) {
    int b = blockIdx.x, dir = blockIdx.y;
    int it = blockIdx.z >> 1, jt = blockIdx.z & 1;
    const float* A = q1 + ((size_t)b * 128 + it * 64) * 512 + dir * 256;
    const float* B = q2 + ((size_t)b * 128 + jt * 64) * 512 + dir * 256;

    __shared__ float n1s[64], n2s[64];
    __shared__ float As[16][64], Bs[16][64];

    int t = threadIdx.x;
    if (t < 128) {
        int r = t & 63;
        const float* src = (t < 64) ? A : B;
        float s = 0.f;
        for (int h = 0; h < 256; h += 4) {
            float4 v = *(const float4*)(src + (size_t)r * 512 + h);
            s += v.x * v.x + v.y * v.y + v.z * v.z + v.w * v.w;
        }
        if (t < 64) n1s[r] = sqrtf(s); else n2s[r] = sqrtf(s);
    }

    int tx = t & 15, ty = t >> 4;
    float acc[4][4] = {};
    int iL = t >> 2, c4 = (t & 3) * 4;

    for (int k0 = 0; k0 < 256; k0 += 16) {
        float4 a  = *(const float4*)(A + (size_t)iL * 512 + k0 + c4);
        float4 bb = *(const float4*)(B + (size_t)iL * 512 + k0 + c4);
        As[c4 + 0][iL] = a.x;  As[c4 + 1][iL] = a.y;
        As[c4 + 2][iL] = a.z;  As[c4 + 3][iL] = a.w;
        Bs[c4 + 0][iL] = bb.x; Bs[c4 + 1][iL] = bb.y;
        Bs[c4 + 2][iL] = bb.z; Bs[c4 + 3][iL] = bb.w;
        __syncthreads();
#pragma unroll
        for (int kk = 0; kk < 16; kk++) {
            float4 ar = *(const float4*)&As[kk][ty * 4];
            float4 br = *(const float4*)&Bs[kk][tx * 4];
            float arr[4] = {ar.x, ar.y, ar.z, ar.w};
            float brr[4] = {br.x, br.y, br.z, br.w};
#pragma unroll
            for (int ii = 0; ii < 4; ii++)
#pragma unroll
                for (int jj = 0; jj < 4; jj++)
                    acc[ii][jj] += arr[ii] * brr[jj];
        }
        __syncthreads();
    }

#pragma unroll
    for (int ii = 0; ii < 4; ii++)
#pragma unroll
        for (int jj = 0; jj < 4; jj++) {
            int i = ty * 4 + ii, j = tx * 4 + jj;
            float den = n1s[i] * n2s[j];
            den = (den > EPS) ? den : EPS;
            g_att[dir][b][it * 64 + i][jt * 64 + j] = acc[ii][jj] / den;
        }
}

// ---------------------------------------------------------------------------
// Kernel 1.5: rowsums of att_fw
// ---------------------------------------------------------------------------
__global__ void k_rowsum() {
    int b = blockIdx.x, i = threadIdx.x;
    float s = 0.f;
    const float* row = &g_att[0][b][i][0];
    for (int j = 0; j < 128; j++) s += row[j];
    g_rowsum_fw[b][i] = s;
}

// ---------------------------------------------------------------------------
// Kernel 2: meanS / maxat
// ---------------------------------------------------------------------------
__global__ void k_meanmax(const float* __restrict__ q2) {
    int b = blockIdx.x, dir = blockIdx.y, iq = blockIdx.z;
    int i0 = iq * 32;
    __shared__ float att_s[32][128];

    const float* src = &g_att[dir][b][i0][0];
    for (int c = threadIdx.x; c < 32 * 128; c += 256)
        ((float*)att_s)[c] = src[c];
    __syncthreads();

    int h = threadIdx.x;
    const float* B = q2 + (size_t)b * 65536 + dir * 256 + h;

    for (int il = 0; il < 32; il += 4) {
        float acc0 = 0.f, acc1 = 0.f, acc2 = 0.f, acc3 = 0.f;
        float mx0 = -INFINITY, mx1 = -INFINITY, mx2 = -INFINITY, mx3 = -INFINITY;
#pragma unroll 4
        for (int j = 0; j < 128; j++) {
            float q = __ldg(B + (size_t)j * 512);
            float v0 = att_s[il + 0][j] * q; acc0 += v0; mx0 = fmaxf(mx0, v0);
            float v1 = att_s[il + 1][j] * q; acc1 += v1; mx1 = fmaxf(mx1, v1);
            float v2 = att_s[il + 2][j] * q; acc2 += v2; mx2 = fmaxf(mx2, v2);
            float v3 = att_s[il + 3][j] * q; acc3 += v3; mx3 = fmaxf(mx3, v3);
        }
        g_meanS[dir][b][i0 + il + 0][h] = acc0;  g_maxat[dir][b][i0 + il + 0][h] = mx0;
        g_meanS[dir][b][i0 + il + 1][h] = acc1;  g_maxat[dir][b][i0 + il + 1][h] = mx1;
        g_meanS[dir][b][i0 + il + 2][h] = acc2;  g_maxat[dir][b][i0 + il + 2][h] = mx2;
        g_meanS[dir][b][i0 + il + 3][h] = acc3;  g_maxat[dir][b][i0 + il + 3][h] = mx3;
    }
}

// ---------------------------------------------------------------------------
// Kernel 3 (HMMA): cos_maxpool. One CTA per (b,p,dir).
// S = (q1 .* w2_p) q2^T via bf16 3-term split: Ah*Bh + Ah*Bl + Al*Bh.
// K=256 in 4 chunks of 64. SMEM tiles [128][72] bf16 (stride 36 words).
// ---------------------------------------------------------------------------
#define TS_W    36                       // padded tile stride in 32-bit words
#define TILE_B  (128 * TS_W * 4)         // 18432 bytes

#define OFF_W2   0
#define OFF_NA   1024
#define OFF_NC   1536
#define OFF_RED  2048
#define OFF_AH   4096
#define OFF_AL   (OFF_AH + TILE_B)
#define OFF_BH   (OFF_AH + 2 * TILE_B)
#define OFF_BL   (OFF_AH + 3 * TILE_B)
#define SMEM_MMA_TOTAL (OFF_AH + 4 * TILE_B)   // 77824

__global__ void __launch_bounds__(256)
k_maxpool_mma(const float* __restrict__ q1, const float* __restrict__ q2,
              const float* __restrict__ W, float* __restrict__ out) {
    extern __shared__ char smem[];
    int b = blockIdx.x, p = blockIdx.y, dir = blockIdx.z;
    int t = threadIdx.x;
    int wid = t >> 5, lane = t & 31;
    int gid = lane >> 2, tig = lane & 3;
    int wr = wid >> 2, wc = wid & 3;       // warp grid 2x4
    int mb = wr * 64, nb = wc * 32;        // warp tile bases

    const float* Ag = q1 + (size_t)b * 65536 + dir * 256;   // row stride 512
    const float* Bg = q2 + (size_t)b * 65536 + dir * 256;
    const float* Wp = W + (size_t)((2 + dir) * 16 + p) * 256;

    float* w2s  = (float*)(smem + OFF_W2);
    float* na_s = (float*)(smem + OFF_NA);
    float* nc_s = (float*)(smem + OFF_NC);
    float* red  = (float*)(smem + OFF_RED);          // [128][4]
    uint32_t* Ah_w = (uint32_t*)(smem + OFF_AH);
    uint32_t* Al_w = (uint32_t*)(smem + OFF_AL);
    uint32_t* Bh_w = (uint32_t*)(smem + OFF_BH);
    uint32_t* Bl_w = (uint32_t*)(smem + OFF_BL);

    { float w = Wp[t]; w2s[t] = w * w; }
    __syncthreads();

    // exact fp32 weighted norms
    {
        int r = t & 127;
        const float* src = (t < 128) ? Ag : Bg;
        float s = 0.f;
        for (int h = 0; h < 256; h += 4) {
            float4 v = *(const float4*)(src + (size_t)r * 512 + h);
            s += v.x * v.x * w2s[h] + v.y * v.y * w2s[h + 1]
               + v.z * v.z * w2s[h + 2] + v.w * v.w * w2s[h + 3];
        }
        if (t < 128) na_s[r] = sqrtf(s); else nc_s[r] = sqrtf(s);
    }

    float acc[4][4][4];
#pragma unroll
    for (int mi = 0; mi < 4; mi++)
#pragma unroll
        for (int ni = 0; ni < 4; ni++)
#pragma unroll
            for (int c = 0; c < 4; c++) acc[mi][ni][c] = 0.f;

    const __nv_bfloat16* q2h_base = g_q2h + ((size_t)b * 128) * 512 + dir * 256;
    const __nv_bfloat16* q2l_base = g_q2l + ((size_t)b * 128) * 512 + dir * 256;

    for (int c = 0; c < 4; c++) {
        int kb = c * 64;
        // ---- convert A chunk (q1 .* w2), split hi/lo ----
#pragma unroll
        for (int r = 0; r < 8; r++) {
            int v = r * 256 + t;             // 0..2047
            int i = v >> 4;                  // row 0..127
            int h4 = (v & 15) * 4;           // 0..60
            float4 qa = *(const float4*)(Ag + (size_t)i * 512 + kb + h4);
            float a0 = qa.x * w2s[kb + h4 + 0];
            float a1 = qa.y * w2s[kb + h4 + 1];
            float a2 = qa.z * w2s[kb + h4 + 2];
            float a3 = qa.w * w2s[kb + h4 + 3];
            __nv_bfloat16 h0 = __float2bfloat16(a0), h1 = __float2bfloat16(a1);
            __nv_bfloat16 h2 = __float2bfloat16(a2), h3 = __float2bfloat16(a3);
            __nv_bfloat16 l0 = __float2bfloat16(a0 - __bfloat162float(h0));
            __nv_bfloat16 l1 = __float2bfloat16(a1 - __bfloat162float(h1));
            __nv_bfloat16 l2 = __float2bfloat16(a2 - __bfloat162float(h2));
            __nv_bfloat16 l3 = __float2bfloat16(a3 - __bfloat162float(h3));
            uint32_t woff = (uint32_t)i * TS_W + (uint32_t)(h4 >> 1);
            uint2 pk;
            pk.x = ((uint32_t)__bfloat16_as_ushort(h1) << 16) | __bfloat16_as_ushort(h0);
            pk.y = ((uint32_t)__bfloat16_as_ushort(h3) << 16) | __bfloat16_as_ushort(h2);
            *(uint2*)(Ah_w + woff) = pk;
            pk.x = ((uint32_t)__bfloat16_as_ushort(l1) << 16) | __bfloat16_as_ushort(l0);
            pk.y = ((uint32_t)__bfloat16_as_ushort(l3) << 16) | __bfloat16_as_ushort(l2);
            *(uint2*)(Al_w + woff) = pk;
        }
        // ---- copy precomputed B chunk (hi/lo bf16) ----
#pragma unroll
        for (int r = 0; r < 8; r++) {
            int v = r * 256 + t;
            int n = v >> 4;
            int kk = (v & 15) * 4;
            uint32_t woff = (uint32_t)n * TS_W + (uint32_t)(kk >> 1);
            *(uint2*)(Bh_w + woff) = *(const uint2*)(q2h_base + (size_t)n * 512 + kb + kk);
            *(uint2*)(Bl_w + woff) = *(const uint2*)(q2l_base + (size_t)n * 512 + kb + kk);
        }
        __syncthreads();

        // ---- MMA over this chunk: 4 k-steps of 16 ----
#pragma unroll
        for (int ks = 0; ks < 4; ks++) {
            int kw = ks * 8;     // k offset in words
            uint32_t bhf[4][2], blf[4][2];
#pragma unroll
            for (int ni = 0; ni < 4; ni++) {
                const uint32_t* ph = Bh_w + (uint32_t)(nb + ni * 8 + gid) * TS_W + kw + tig;
                bhf[ni][0] = ph[0]; bhf[ni][1] = ph[4];
                const uint32_t* pl = Bl_w + (uint32_t)(nb + ni * 8 + gid) * TS_W + kw + tig;
                blf[ni][0] = pl[0]; blf[ni][1] = pl[4];
            }
#pragma unroll
            for (int mi = 0; mi < 4; mi++) {
                const uint32_t* pa = Ah_w + (uint32_t)(mb + mi * 16 + gid) * TS_W + kw + tig;
                uint32_t ah[4];
                ah[0] = pa[0]; ah[1] = pa[8 * TS_W];
                ah[2] = pa[4]; ah[3] = pa[8 * TS_W + 4];
                const uint32_t* pl = Al_w + (uint32_t)(mb + mi * 16 + gid) * TS_W + kw + tig;
                uint32_t al[4];
                al[0] = pl[0]; al[1] = pl[8 * TS_W];
                al[2] = pl[4]; al[3] = pl[8 * TS_W + 4];
#pragma unroll
                for (int ni = 0; ni < 4; ni++) {
                    mma16816(acc[mi][ni], ah, bhf[ni]);
                    mma16816(acc[mi][ni], ah, blf[ni]);
                    mma16816(acc[mi][ni], al, bhf[ni]);
                }
            }
        }
        __syncthreads();
    }

    // ---- epilogue: cos divide + row max ----
    float nc_v[4][2];
#pragma unroll
    for (int ni = 0; ni < 4; ni++) {
        int cb = nb + ni * 8 + 2 * tig;
        nc_v[ni][0] = nc_s[cb];
        nc_v[ni][1] = nc_s[cb + 1];
    }
#pragma unroll
    for (int mi = 0; mi < 4; mi++) {
        int r0 = mb + mi * 16 + gid;
        float na0 = na_s[r0], na1 = na_s[r0 + 8];
        float m0 = -INFINITY, m1 = -INFINITY;
#pragma unroll
        for (int ni = 0; ni < 4; ni++) {
            m0 = fmaxf(m0, acc[mi][ni][0] / fmaxf(na0 * nc_v[ni][0], EPS));
            m0 = fmaxf(m0, acc[mi][ni][1] / fmaxf(na0 * nc_v[ni][1], EPS));
            m1 = fmaxf(m1, acc[mi][ni][2] / fmaxf(na1 * nc_v[ni][0], EPS));
            m1 = fmaxf(m1, acc[mi][ni][3] / fmaxf(na1 * nc_v[ni][1], EPS));
        }
        m0 = fmaxf(m0, __shfl_xor_sync(0xffffffffu, m0, 1));
        m0 = fmaxf(m0, __shfl_xor_sync(0xffffffffu, m0, 2));
        m1 = fmaxf(m1, __shfl_xor_sync(0xffffffffu, m1, 1));
        m1 = fmaxf(m1, __shfl_xor_sync(0xffffffffu, m1, 2));
        if (tig == 0) {
            red[r0 * 4 + wc] = m0;
            red[(r0 + 8) * 4 + wc] = m1;
        }
    }
    __syncthreads();
    if (t < 128) {
        float m = red[t * 4 + 0];
        m = fmaxf(m, red[t * 4 + 1]);
        m = fmaxf(m, red[t * 4 + 2]);
        m = fmaxf(m, red[t * 4 + 3]);
        out[((size_t)b * 128 + t) * 128 + 32 + dir * 16 + p] = m;
    }
}

// ---------------------------------------------------------------------------
// Kernel 4: the six cos_full outputs
// ---------------------------------------------------------------------------
__global__ void k_cosfull(const float* __restrict__ q1, const float* __restrict__ q2,
                          const float* __restrict__ W, float* __restrict__ out) {
    int i = blockIdx.x, b = blockIdx.y;
    int lane = threadIdx.x & 31, warp = threadIdx.x >> 5;

    for (int s = 0; s < 12; s++) {
        int tk = warp + 8 * s;
        int p = tk & 15;
        int rest = tk >> 4;
        int dir = rest & 1, which = rest >> 1;
        int widx = (which == 0) ? dir : ((which == 1) ? 4 + dir : 6 + dir);
        const float* wv = W + (size_t)(widx * 16 + p) * 256;
        const float* x  = q1 + (size_t)b * 65536 + (size_t)i * 512 + dir * 256;
        const float* y;
        float sy = 1.f;
        if (which == 0) {
            int j = (dir == 0) ? 127 : 0;
            y = q2 + (size_t)b * 65536 + (size_t)j * 512 + dir * 256;
        } else if (which == 1) {
            y = &g_meanS[dir][b][i][0];
            float rs = g_rowsum_fw[b][i];
            float bsafe = (rs > EPS) ? rs : EPS;
            sy = 1.f / bsafe;
        } else {
            y = &g_maxat[dir][b][i][0];
        }

        float sxy = 0.f, sxx = 0.f, syy = 0.f;
        for (int h = lane; h < 256; h += 32) {
            float w = wv[h]; float ww = w * w;
            float xv = x[h];
            float yv = y[h] * sy;
            sxy += xv * yv * ww;
            sxx += xv * xv * ww;
            syy += yv * yv * ww;
        }
#pragma unroll
        for (int off = 16; off > 0; off >>= 1) {
            sxy += __shfl_xor_sync(0xffffffffu, sxy, off);
            sxx += __shfl_xor_sync(0xffffffffu, sxx, off);
            syy += __shfl_xor_sync(0xffffffffu, syy, off);
        }
        if (lane == 0) {
            float den = fmaxf(sqrtf(sxx) * sqrtf(syy), EPS);
            int col = ((which == 0) ? 0 : (which == 1) ? 64 : 96) + dir * 16 + p;
            out[((size_t)b * 128 + i) * 128 + col] = sxy / den;
        }
    }
}

// ---------------------------------------------------------------------------
extern "C" void kernel_launch(void* const* d_in, const int* in_sizes, int n_in,
                              void* d_out, int out_size) {
    const float* q1 = (const float*)d_in[0];
    const float* q2 = (const float*)d_in[1];
    const float* W  = (const float*)d_in[2];
    float* out = (float*)d_out;

    cudaFuncSetAttribute(k_maxpool_mma, cudaFuncAttributeMaxDynamicSharedMemorySize,
                         SMEM_MMA_TOTAL);

    k_split_q2<<<1024, 256>>>(q2);
    k_attention<<<dim3(16, 2, 4), 256>>>(q1, q2);
    k_rowsum<<<16, 128>>>();
    k_meanmax<<<dim3(16, 2, 4), 256>>>(q2);
    k_maxpool_mma<<<dim3(16, 16, 2), 256, SMEM_MMA_TOTAL>>>(q1, q2, W, out);
    k_cosfull<<<dim3(128, 16), 256>>>(q1, q2, W, out);
}